// round 3
// baseline (speedup 1.0000x reference)
#include <cuda_runtime.h>

typedef unsigned long long ull;

#define NN 20000
#define NE 320000
#define ET (NE+NN)
#define BB 128
#define TT 200

__device__ __forceinline__ ull fma2(ull a, ull b, ull c){
  ull d; asm("fma.rn.f32x2 %0, %1, %2, %3;" : "=l"(d) : "l"(a), "l"(b), "l"(c)); return d;
}
__device__ __forceinline__ ull pack2(float lo, float hi){
  ull d; asm("mov.b64 %0, {%1, %2};" : "=l"(d) : "f"(lo), "f"(hi)); return d;
}
__device__ __forceinline__ void unpack2(ull v, float& lo, float& hi){
  asm("mov.b64 {%0, %1}, %2;" : "=f"(lo), "=f"(hi) : "l"(v));
}
__device__ __forceinline__ float hsum2(ull v){
  float lo, hi; unpack2(v, lo, hi); return lo + hi;
}
__device__ __forceinline__ float sigf(float x){ return 1.f/(1.f+__expf(-x)); }

// ---------------- scratch (device globals; no allocs) ----------------
__device__ float g_nf[NN*144];
__device__ float g_w1p[144*256];
__device__ float g_h1[NN*256];
__device__ float g_z1[NN*256];
__device__ float g_as1[NN*4];
__device__ float g_ad1[NN*4];
__device__ float g_h2[NN*128];
__device__ float g_z2[NN*128];
__device__ float g_as2[NN];
__device__ float g_ad2[NN];
__device__ int   g_cnt[NN];
__device__ int   g_fill[NN];
__device__ int   g_rowptr[NN+1];
__device__ int   g_srcs[ET];
__device__ float g_wTih[2][128*512];
__device__ float g_seqg[2][BB*TT*128];
__device__ float g_xproj[2][BB*TT*512];
__device__ float g_lstm[BB*TT*256];
__device__ float g_ctx[2][BB*256];

// ---------------- prep: padded features, padded W1, w_ih transpose ----------------
__global__ void k_prep(const float* __restrict__ xc, const float* __restrict__ tf,
                       const float* __restrict__ emb, const float* __restrict__ W1,
                       const float* __restrict__ wihf, const float* __restrict__ wihb){
  int i = blockIdx.x*256 + threadIdx.x;
  if (i < NN*144){
    int r = i/144, c = i - r*144;
    float v = 0.f;
    if (c < 2)        v = xc[r*2 + c];
    else if (c < 130) v = emb[r*128 + (c-2)];
    else if (c < 134) v = tf[r*4 + (c-130)];
    g_nf[i] = v;
  }
  if (i < 144*256) g_w1p[i] = (i < 134*256) ? W1[i] : 0.f;
  if (i < 128*512){
    int k = i >> 9, g = i & 511;
    g_wTih[0][i] = wihf[g*128 + k];
    g_wTih[1][i] = wihb[g*128 + k];
  }
}

__global__ void k_zero_lstm(){
  int i = blockIdx.x*256 + threadIdx.x;
  if (i < BB*TT*256) g_lstm[i] = 0.f;
}

// ---------------- CSR build (deterministic: ids sorted per segment) ----------------
__global__ void k_zero_cnt(){
  int i = blockIdx.x*256 + threadIdx.x;
  if (i < NN){ g_cnt[i] = 0; g_fill[i] = 0; }
}
__global__ void k_count(const int* __restrict__ ei){
  int e = blockIdx.x*256 + threadIdx.x;
  if (e >= ET) return;
  int d = (e < NE) ? ei[NE + e] : (e - NE);
  atomicAdd(&g_cnt[d], 1);
}
__global__ void k_scan(){
  __shared__ int ps[1024];
  int tid = threadIdx.x;
  int base = tid*20;
  int sum = 0;
  for (int j = 0; j < 20; j++){ int i = base + j; if (i < NN) sum += g_cnt[i]; }
  ps[tid] = sum;
  __syncthreads();
  for (int off = 1; off < 1024; off <<= 1){
    int v = (tid >= off) ? ps[tid-off] : 0;
    __syncthreads();
    ps[tid] += v;
    __syncthreads();
  }
  int run = ps[tid] - sum;     // exclusive prefix
  for (int j = 0; j < 20; j++){ int i = base + j; if (i < NN){ g_rowptr[i] = run; run += g_cnt[i]; } }
  if (tid == 0) g_rowptr[NN] = ET;
}
__global__ void k_scatter(const int* __restrict__ ei){
  int e = blockIdx.x*256 + threadIdx.x;
  if (e >= ET) return;
  int d = (e < NE) ? ei[NE + e] : (e - NE);
  int p = atomicAdd(&g_fill[d], 1);
  g_srcs[g_rowptr[d] + p] = e;               // store edge id (sorted below)
}
__global__ void k_sortseg(const int* __restrict__ ei){
  __shared__ int buf[8][128];
  int wid = threadIdx.x >> 5, lane = threadIdx.x & 31;
  int n = blockIdx.x*8 + wid;
  if (n >= NN) return;
  int r0 = g_rowptr[n], r1 = g_rowptr[n+1], d = r1 - r0;
  if (d <= 128){
    for (int j = lane; j < d; j += 32) buf[wid][j] = g_srcs[r0 + j];
    __syncwarp();
    if (lane == 0){
      for (int a = 1; a < d; a++){
        int v = buf[wid][a]; int b = a - 1;
        while (b >= 0 && buf[wid][b] > v){ buf[wid][b+1] = buf[wid][b]; b--; }
        buf[wid][b+1] = v;
      }
    }
    __syncwarp();
    for (int j = lane; j < d; j += 32){
      int id = buf[wid][j];
      g_srcs[r0 + j] = (id < NE) ? ei[id] : (id - NE);
    }
  } else {
    for (int j = lane; j < d; j += 32){
      int id = g_srcs[r0 + j];
      g_srcs[r0 + j] = (id < NE) ? ei[id] : (id - NE);
    }
  }
}

// ---------------- f32x2 SGEMM: C = A[MxK] @ B[KxN] (+ bias over N) ----------------
// 64x64 tile, 256 threads, 4Mx4N micro-tile as 2x(f32x2 M-pair) x 4N.
// B held in smem pre-duplicated as (b,b) pairs so the inner loop is pure FFMA2.
__global__ void k_gemm(const float* __restrict__ A, const float* __restrict__ B,
                       const float* __restrict__ bias, float* __restrict__ C,
                       int M, int N, int K){
  __shared__ float As[16][64];
  __shared__ ull   Bsd[16][64];
  int bn = blockIdx.x*64, bm = blockIdx.y*64;
  int tid = threadIdx.x;
  int tx = tid & 15, ty = tid >> 4;
  ull acc[2][4];
  #pragma unroll
  for (int i = 0; i < 2; i++)
    #pragma unroll
    for (int j = 0; j < 4; j++) acc[i][j] = 0ULL;

  int ar = tid >> 2, ak = (tid & 3) << 2;     // A tile: 64 rows x 16 k
  int bk = tid >> 4, bn2 = (tid & 15) << 2;   // B tile: 16 k x 64 n

  for (int k0 = 0; k0 < K; k0 += 16){
    float4 av = make_float4(0.f,0.f,0.f,0.f);
    if (bm + ar < M) av = *(const float4*)(A + (size_t)(bm + ar)*K + k0 + ak);
    As[ak  ][ar] = av.x; As[ak+1][ar] = av.y; As[ak+2][ar] = av.z; As[ak+3][ar] = av.w;
    float4 bv = make_float4(0.f,0.f,0.f,0.f);
    if (bn + bn2 < N) bv = *(const float4*)(B + (size_t)(k0 + bk)*N + bn + bn2);
    ulonglong2 d0, d1;
    d0.x = pack2(bv.x, bv.x); d0.y = pack2(bv.y, bv.y);
    d1.x = pack2(bv.z, bv.z); d1.y = pack2(bv.w, bv.w);
    *(ulonglong2*)&Bsd[bk][bn2]     = d0;
    *(ulonglong2*)&Bsd[bk][bn2 + 2] = d1;
    __syncthreads();
    #pragma unroll
    for (int kk = 0; kk < 16; kk++){
      ulonglong2 a = *(const ulonglong2*)&As[kk][ty << 2];      // rows (4ty,4ty+1),(4ty+2,4ty+3)
      ulonglong2 b0 = *(const ulonglong2*)&Bsd[kk][tx << 1];    // cols 2tx, 2tx+1 (dup)
      ulonglong2 b1 = *(const ulonglong2*)&Bsd[kk][(tx << 1) + 32]; // cols 2tx+32, 2tx+33
      acc[0][0] = fma2(a.x, b0.x, acc[0][0]);
      acc[1][0] = fma2(a.y, b0.x, acc[1][0]);
      acc[0][1] = fma2(a.x, b0.y, acc[0][1]);
      acc[1][1] = fma2(a.y, b0.y, acc[1][1]);
      acc[0][2] = fma2(a.x, b1.x, acc[0][2]);
      acc[1][2] = fma2(a.y, b1.x, acc[1][2]);
      acc[0][3] = fma2(a.x, b1.y, acc[0][3]);
      acc[1][3] = fma2(a.y, b1.y, acc[1][3]);
    }
    __syncthreads();
  }
  int cols[4];
  cols[0] = bn + (tx << 1);      cols[1] = cols[0] + 1;
  cols[2] = cols[0] + 32;        cols[3] = cols[2] + 1;
  #pragma unroll
  for (int mi = 0; mi < 2; mi++){
    int rlo = bm + (ty << 2) + (mi << 1);
    #pragma unroll
    for (int j = 0; j < 4; j++){
      float lo, hi; unpack2(acc[mi][j], lo, hi);
      int col = cols[j];
      if (col >= N) continue;
      float bv = bias ? bias[col] : 0.f;
      if (rlo < M)     C[(size_t)rlo*N + col]     = lo + bv;
      if (rlo + 1 < M) C[(size_t)(rlo+1)*N + col] = hi + bv;
    }
  }
}

// ---------------- attention dots ----------------
__global__ void k_attdot1(const float* __restrict__ aw_s, const float* __restrict__ aw_d){
  int i = blockIdx.x*256 + threadIdx.x;
  if (i >= NN*4) return;
  int n = i >> 2, h = i & 3;
  const float4* hp = (const float4*)(g_h1 + n*256 + h*64);
  const float4* sw = (const float4*)(aw_s + h*64);
  const float4* dw = (const float4*)(aw_d + h*64);
  float s = 0.f, d = 0.f;
  #pragma unroll
  for (int j = 0; j < 16; j++){
    float4 x = hp[j], a = sw[j], b = dw[j];
    s += x.x*a.x + x.y*a.y + x.z*a.z + x.w*a.w;
    d += x.x*b.x + x.y*b.y + x.z*b.z + x.w*b.w;
  }
  g_as1[i] = s; g_ad1[i] = d;
}
__global__ void k_attdot2(const float* __restrict__ aw_s, const float* __restrict__ aw_d){
  int n = blockIdx.x*256 + threadIdx.x;
  if (n >= NN) return;
  const float4* hp = (const float4*)(g_h2 + n*128);
  const float4* sw = (const float4*)aw_s;
  const float4* dw = (const float4*)aw_d;
  float s = 0.f, d = 0.f;
  #pragma unroll
  for (int j = 0; j < 32; j++){
    float4 x = hp[j], a = sw[j], b = dw[j];
    s += x.x*a.x + x.y*a.y + x.z*a.z + x.w*a.w;
    d += x.x*b.x + x.y*b.y + x.z*b.z + x.w*b.w;
  }
  g_as2[n] = s; g_ad2[n] = d;
}

// ---------------- edge softmax + aggregation, layer 1 (4 heads x 64) ----------------
__global__ void k_agg1(const float* __restrict__ bias){
  int wid = threadIdx.x >> 5, lane = threadIdx.x & 31;
  int n = blockIdx.x*8 + wid;
  int r0 = g_rowptr[n], r1 = g_rowptr[n+1];
  float4 ad = *(const float4*)(g_ad1 + n*4);
  float m0 = -1e30f, m1 = -1e30f, m2 = -1e30f, m3 = -1e30f;
  for (int e = r0 + lane; e < r1; e += 32){
    int s = g_srcs[e];
    float4 as = *(const float4*)(g_as1 + s*4);
    float v0 = as.x + ad.x; v0 = v0 > 0.f ? v0 : 0.2f*v0;
    float v1 = as.y + ad.y; v1 = v1 > 0.f ? v1 : 0.2f*v1;
    float v2 = as.z + ad.z; v2 = v2 > 0.f ? v2 : 0.2f*v2;
    float v3 = as.w + ad.w; v3 = v3 > 0.f ? v3 : 0.2f*v3;
    m0 = fmaxf(m0, v0); m1 = fmaxf(m1, v1); m2 = fmaxf(m2, v2); m3 = fmaxf(m3, v3);
  }
  #pragma unroll
  for (int o = 16; o; o >>= 1){
    m0 = fmaxf(m0, __shfl_xor_sync(0xffffffffu, m0, o));
    m1 = fmaxf(m1, __shfl_xor_sync(0xffffffffu, m1, o));
    m2 = fmaxf(m2, __shfl_xor_sync(0xffffffffu, m2, o));
    m3 = fmaxf(m3, __shfl_xor_sync(0xffffffffu, m3, o));
  }
  float s0 = 0.f, s1 = 0.f, s2 = 0.f, s3 = 0.f;
  for (int e = r0 + lane; e < r1; e += 32){
    int s = g_srcs[e];
    float4 as = *(const float4*)(g_as1 + s*4);
    float v0 = as.x + ad.x; v0 = v0 > 0.f ? v0 : 0.2f*v0;
    float v1 = as.y + ad.y; v1 = v1 > 0.f ? v1 : 0.2f*v1;
    float v2 = as.z + ad.z; v2 = v2 > 0.f ? v2 : 0.2f*v2;
    float v3 = as.w + ad.w; v3 = v3 > 0.f ? v3 : 0.2f*v3;
    s0 += __expf(v0 - m0); s1 += __expf(v1 - m1);
    s2 += __expf(v2 - m2); s3 += __expf(v3 - m3);
  }
  #pragma unroll
  for (int o = 16; o; o >>= 1){
    s0 += __shfl_xor_sync(0xffffffffu, s0, o);
    s1 += __shfl_xor_sync(0xffffffffu, s1, o);
    s2 += __shfl_xor_sync(0xffffffffu, s2, o);
    s3 += __shfl_xor_sync(0xffffffffu, s3, o);
  }
  int hsel = lane >> 3;                                    // head owning this lane's 8 channels
  float mh  = hsel == 0 ? m0 : hsel == 1 ? m1 : hsel == 2 ? m2 : m3;
  float inv = 1.f / (hsel == 0 ? s0 : hsel == 1 ? s1 : hsel == 2 ? s2 : s3);
  float adh = hsel == 0 ? ad.x : hsel == 1 ? ad.y : hsel == 2 ? ad.z : ad.w;
  float a0=0,a1=0,a2=0,a3=0,a4=0,a5=0,a6=0,a7=0;
  for (int e = r0; e < r1; e++){
    int s = g_srcs[e];
    float v = g_as1[s*4 + hsel] + adh; v = v > 0.f ? v : 0.2f*v;
    float alpha = __expf(v - mh) * inv;
    const float4* xp = (const float4*)(g_h1 + s*256 + lane*8);
    float4 x0 = xp[0], x1 = xp[1];
    a0 += alpha*x0.x; a1 += alpha*x0.y; a2 += alpha*x0.z; a3 += alpha*x0.w;
    a4 += alpha*x1.x; a5 += alpha*x1.y; a6 += alpha*x1.z; a7 += alpha*x1.w;
  }
  int cb = lane*8;
  float* outp = g_z1 + n*256 + cb;
  float r[8] = {a0,a1,a2,a3,a4,a5,a6,a7};
  #pragma unroll
  for (int i = 0; i < 8; i++){
    float o = r[i] + bias[cb + i];
    outp[i] = o > 0.f ? o : expm1f(o);                     // ELU
  }
}

// ---------------- edge softmax + aggregation, layer 2 (1 head x 128) ----------------
__global__ void k_agg2(const float* __restrict__ bias){
  int wid = threadIdx.x >> 5, lane = threadIdx.x & 31;
  int n = blockIdx.x*8 + wid;
  int r0 = g_rowptr[n], r1 = g_rowptr[n+1];
  float ad = g_ad2[n];
  float m = -1e30f;
  for (int e = r0 + lane; e < r1; e += 32){
    float v = g_as2[g_srcs[e]] + ad; v = v > 0.f ? v : 0.2f*v;
    m = fmaxf(m, v);
  }
  #pragma unroll
  for (int o = 16; o; o >>= 1) m = fmaxf(m, __shfl_xor_sync(0xffffffffu, m, o));
  float ssum = 0.f;
  for (int e = r0 + lane; e < r1; e += 32){
    float v = g_as2[g_srcs[e]] + ad; v = v > 0.f ? v : 0.2f*v;
    ssum += __expf(v - m);
  }
  #pragma unroll
  for (int o = 16; o; o >>= 1) ssum += __shfl_xor_sync(0xffffffffu, ssum, o);
  float inv = 1.f / ssum;
  float a0=0,a1=0,a2=0,a3=0;
  for (int e = r0; e < r1; e++){
    int s = g_srcs[e];
    float v = g_as2[s] + ad; v = v > 0.f ? v : 0.2f*v;
    float alpha = __expf(v - m) * inv;
    float4 x = *(const float4*)(g_h2 + s*128 + lane*4);
    a0 += alpha*x.x; a1 += alpha*x.y; a2 += alpha*x.z; a3 += alpha*x.w;
  }
  int cb = lane*4;
  float* outp = g_z2 + n*128 + cb;
  outp[0] = a0 + bias[cb+0];
  outp[1] = a1 + bias[cb+1];
  outp[2] = a2 + bias[cb+2];
  outp[3] = a3 + bias[cb+3];
}

// ---------------- sequence gather (forward + reversed-within-length) ----------------
__global__ void k_gather(const int* __restrict__ seq, const int* __restrict__ lengths){
  int i = blockIdx.x*256 + threadIdx.x;                    // one float4 per thread
  if (i >= BB*TT*32) return;
  int row = i >> 5, q = i & 31;
  int b = row / TT, t = row - b*TT;
  const float4* z = (const float4*)g_z2;
  int sf = seq[row];
  ((float4*)g_seqg[0])[row*32 + q] = z[(size_t)sf*32 + q];
  int len = lengths[b];
  int tr = len - 1 - t; if (tr < 0) tr = 0;
  int sb = seq[b*TT + tr];
  ((float4*)g_seqg[1])[row*32 + q] = z[(size_t)sb*32 + q];
}

// ---------------- BiLSTM recurrence ----------------
__global__ void __launch_bounds__(512, 1)
k_lstm(const float* __restrict__ whhf, const float* __restrict__ whhb,
       const int* __restrict__ lengths){
  extern __shared__ char smraw[];
  ull*   ws  = (ull*)smraw;                 // [512][33] packed f32x2 weight pairs (k 64..127)
  float* hsm = (float*)(ws + 512*33);       // [2][128]
  float* gsm = hsm + 256;                   // [2][512]
  int g   = threadIdx.x;
  int dir = blockIdx.y;
  int b0  = blockIdx.x*2;
  const float* whh = dir ? whhb : whhf;
  const ull* wrow = (const ull*)(whh + g*128);
  ull wreg[32];
  #pragma unroll
  for (int j = 0; j < 32; j++) wreg[j] = wrow[j];          // k pairs 0..31
  #pragma unroll
  for (int j = 0; j < 32; j++) ws[g*33 + j] = wrow[32 + j];// k pairs 32..63
  if (g < 256) hsm[g] = 0.f;
  float cc = 0.f;
  int len0 = lengths[b0], len1 = lengths[b0+1];
  int Tn = len0 > len1 ? len0 : len1;       // both dirs: t >= len has zero softmax weight
  const float* x0p = g_xproj[dir] + (size_t)b0*TT*512;
  const float* x1p = x0p + (size_t)TT*512;
  __syncthreads();
  for (int t = 0; t < Tn; t++){
    float xv0 = x0p[t*512 + g];
    float xv1 = x1p[t*512 + g];
    ull a0 = 0ULL, a1 = 0ULL;
    const ull* h0p = (const ull*)hsm;
    const ull* h1p = (const ull*)(hsm + 128);
    #pragma unroll
    for (int j = 0; j < 32; j++){
      ull w = wreg[j];
      a0 = fma2(w, h0p[j], a0);
      a1 = fma2(w, h1p[j], a1);
    }
    #pragma unroll
    for (int j = 0; j < 32; j++){
      ull w = ws[g*33 + j];
      a0 = fma2(w, h0p[32 + j], a0);
      a1 = fma2(w, h1p[32 + j], a1);
    }
    gsm[g]       = hsum2(a0) + xv0;
    gsm[512 + g] = hsum2(a1) + xv1;
    __syncthreads();
    if (g < 256){
      int b = g >> 7, j = g & 127;
      const float* gb = gsm + b*512;
      float gi = gb[j], gf = gb[128 + j], gg = gb[256 + j], go = gb[384 + j];
      cc = sigf(gf)*cc + sigf(gi)*tanhf(gg);
      float h = sigf(go)*tanhf(cc);
      hsm[b*128 + j] = h;
      if (dir == 0){
        g_lstm[((size_t)(b0 + b)*TT + t)*256 + j] = h;
      } else {
        int L = b ? len1 : len0;
        if (t < L) g_lstm[((size_t)(b0 + b)*TT + (L - 1 - t))*256 + 128 + j] = h;
      }
    }
    __syncthreads();
  }
}

// ---------------- masked attention pooling (both heads) ----------------
__global__ void k_attnpool(const float* __restrict__ wn, const float* __restrict__ bn,
                           const float* __restrict__ wsp, const float* __restrict__ bsp,
                           const int* __restrict__ lengths){
  __shared__ float sc[256];
  __shared__ float red[256];
  int b = blockIdx.x, p = blockIdx.y;
  const float* w = p ? wsp : wn;
  float bias = p ? bsp[0] : bn[0];
  int tid = threadIdx.x;
  int len = lengths[b];
  float sv = -1e30f;
  if (tid < TT && tid < len){
    const float4* row = (const float4*)(g_lstm + ((size_t)b*TT + tid)*256);
    const float4* wv = (const float4*)w;
    float s = 0.f;
    #pragma unroll
    for (int j = 0; j < 64; j++){
      float4 x = row[j], y = wv[j];
      s += x.x*y.x + x.y*y.y + x.z*y.z + x.w*y.w;
    }
    sv = s + bias;
  }
  red[tid] = sv;
  __syncthreads();
  #pragma unroll
  for (int o = 128; o; o >>= 1){ if (tid < o) red[tid] = fmaxf(red[tid], red[tid+o]); __syncthreads(); }
  float m = red[0];
  __syncthreads();
  float e = (sv <= -1e29f) ? 0.f : __expf(sv - m);
  sc[tid] = e; red[tid] = e;
  __syncthreads();
  #pragma unroll
  for (int o = 128; o; o >>= 1){ if (tid < o) red[tid] += red[tid+o]; __syncthreads(); }
  float inv = 1.f / red[0];
  float acc = 0.f;
  for (int t = 0; t < TT; t++)
    acc += sc[t] * g_lstm[((size_t)b*TT + t)*256 + tid];
  g_ctx[p][b*256 + tid] = acc * inv;
}

// ---------------- launch ----------------
extern "C" void kernel_launch(void* const* d_in, const int* in_sizes, int n_in,
                              void* d_out, int out_size){
  const float* xc   = (const float*)d_in[0];
  const float* tf   = (const float*)d_in[1];
  const float* emb  = (const float*)d_in[2];
  const float* g1W  = (const float*)d_in[3];
  const float* g1as = (const float*)d_in[4];
  const float* g1ad = (const float*)d_in[5];
  const float* g1b  = (const float*)d_in[6];
  const float* g2W  = (const float*)d_in[7];
  const float* g2as = (const float*)d_in[8];
  const float* g2ad = (const float*)d_in[9];
  const float* g2b  = (const float*)d_in[10];
  const float* wihf = (const float*)d_in[11];
  const float* whhf = (const float*)d_in[12];
  const float* bf   = (const float*)d_in[13];
  const float* wihb = (const float*)d_in[14];
  const float* whhb = (const float*)d_in[15];
  const float* bb   = (const float*)d_in[16];
  const float* anw  = (const float*)d_in[17];
  const float* anb  = (const float*)d_in[18];
  const float* asw  = (const float*)d_in[19];
  const float* asb  = (const float*)d_in[20];
  const float* fnW  = (const float*)d_in[21];
  const float* fnb  = (const float*)d_in[22];
  const float* fsW  = (const float*)d_in[23];
  const float* fsb  = (const float*)d_in[24];
  const int*   ei   = (const int*)d_in[25];
  const int*   seq  = (const int*)d_in[26];
  const int*   len  = (const int*)d_in[27];
  float* out = (float*)d_out;

  float *p_nf, *p_w1p, *p_h1, *p_z1, *p_h2, *p_wT, *p_sq, *p_xp, *p_ctx;
  cudaGetSymbolAddress((void**)&p_nf,  g_nf);
  cudaGetSymbolAddress((void**)&p_w1p, g_w1p);
  cudaGetSymbolAddress((void**)&p_h1,  g_h1);
  cudaGetSymbolAddress((void**)&p_z1,  g_z1);
  cudaGetSymbolAddress((void**)&p_h2,  g_h2);
  cudaGetSymbolAddress((void**)&p_wT,  g_wTih);
  cudaGetSymbolAddress((void**)&p_sq,  g_seqg);
  cudaGetSymbolAddress((void**)&p_xp,  g_xproj);
  cudaGetSymbolAddress((void**)&p_ctx, g_ctx);

  k_prep<<<11250, 256>>>(xc, tf, emb, g1W, wihf, wihb);
  k_zero_lstm<<<25600, 256>>>();
  k_zero_cnt<<<(NN+255)/256, 256>>>();
  k_count<<<(ET+255)/256, 256>>>(ei);
  k_scan<<<1, 1024>>>();
  k_scatter<<<(ET+255)/256, 256>>>(ei);
  k_sortseg<<<2500, 256>>>(ei);

  // GAT layer 1
  k_gemm<<<dim3(4, 313), 256>>>(p_nf, p_w1p, nullptr, p_h1, NN, 256, 144);
  k_attdot1<<<(NN*4+255)/256, 256>>>(g1as, g1ad);
  k_agg1<<<2500, 256>>>(g1b);

  // GAT layer 2
  k_gemm<<<dim3(2, 313), 256>>>(p_z1, g2W, nullptr, p_h2, NN, 128, 256);
  k_attdot2<<<(NN+255)/256, 256>>>(g2as, g2ad);
  k_agg2<<<2500, 256>>>(g2b);

  // gather + x-projections (bias folded in)
  k_gather<<<3200, 256>>>(seq, len);
  k_gemm<<<dim3(8, 400), 256>>>(p_sq,               p_wT,           bf, p_xp,               BB*TT, 512, 128);
  k_gemm<<<dim3(8, 400), 256>>>(p_sq + BB*TT*128,   p_wT + 128*512, bb, p_xp + BB*TT*512,   BB*TT, 512, 128);

  // BiLSTM
  int lstm_smem = 512*33*8 + 256*4 + 1024*4;
  cudaFuncSetAttribute(k_lstm, cudaFuncAttributeMaxDynamicSharedMemorySize, lstm_smem);
  k_lstm<<<dim3(64, 2), 512, lstm_smem>>>(whhf, whhb, len);

  // attention pooling + output heads
  k_attnpool<<<dim3(BB, 2), 256>>>(anw, anb, asw, asb, len);
  k_gemm<<<dim3(313, 2), 256>>>(p_ctx,          fnW, fnb, out,                    BB, 20000, 256);
  k_gemm<<<dim3(1, 2),   256>>>(p_ctx + BB*256, fsW, fsb, out + (size_t)BB*20000, BB, 64,    256);
}

// round 4
// speedup vs baseline: 1.1803x; 1.1803x over previous
#include <cuda_runtime.h>

typedef unsigned long long ull;

#define NN 20000
#define NE 320000
#define ET (NE+NN)
#define BB 128
#define TT 200

__device__ __forceinline__ ull fma2(ull a, ull b, ull c){
  ull d; asm("fma.rn.f32x2 %0, %1, %2, %3;" : "=l"(d) : "l"(a), "l"(b), "l"(c)); return d;
}
__device__ __forceinline__ float hsum2(ull v){
  float lo, hi; asm("mov.b64 {%0, %1}, %2;" : "=f"(lo), "=f"(hi) : "l"(v)); return lo + hi;
}
__device__ __forceinline__ float sigf(float x){ return 1.f/(1.f+__expf(-x)); }

// ---------------- scratch (device globals; no allocs) ----------------
__device__ float g_nf[NN*144];
__device__ float g_w1p[144*256];
__device__ float g_h1[NN*256];
__device__ float g_z1[NN*256];
__device__ float g_as1[NN*4];
__device__ float g_ad1[NN*4];
__device__ float g_h2[NN*128];
__device__ float g_z2[NN*128];
__device__ float g_as2[NN];
__device__ float g_ad2[NN];
__device__ int   g_cnt[NN];
__device__ int   g_fill[NN];
__device__ int   g_rowptr[NN+1];
__device__ int   g_srcs[ET];
__device__ float g_wTih[2][128*512];
__device__ float g_seqg[2][BB*TT*128];
__device__ float g_xproj[2][BB*TT*512];
__device__ float g_lstm[BB*TT*256];
__device__ float g_ctx[2][BB*256];

// ---------------- prep: padded features, padded W1, w_ih transpose ----------------
__global__ void k_prep(const float* __restrict__ xc, const float* __restrict__ tf,
                       const float* __restrict__ emb, const float* __restrict__ W1,
                       const float* __restrict__ wihf, const float* __restrict__ wihb){
  int i = blockIdx.x*256 + threadIdx.x;
  if (i < NN*144){
    int r = i/144, c = i - r*144;
    float v = 0.f;
    if (c < 2)        v = xc[r*2 + c];
    else if (c < 130) v = emb[r*128 + (c-2)];
    else if (c < 134) v = tf[r*4 + (c-130)];
    g_nf[i] = v;
  }
  if (i < 144*256) g_w1p[i] = (i < 134*256) ? W1[i] : 0.f;
  if (i < 128*512){
    int k = i >> 9, g = i & 511;
    g_wTih[0][i] = wihf[g*128 + k];
    g_wTih[1][i] = wihb[g*128 + k];
  }
}

// ---------------- CSR build (deterministic: ids sorted per segment) ----------------
__global__ void k_zero_cnt(){
  int i = blockIdx.x*256 + threadIdx.x;
  if (i < NN){ g_cnt[i] = 0; g_fill[i] = 0; }
}
__global__ void k_count(const int* __restrict__ ei){
  int e = blockIdx.x*256 + threadIdx.x;
  if (e >= ET) return;
  int d = (e < NE) ? ei[NE + e] : (e - NE);
  atomicAdd(&g_cnt[d], 1);
}
__global__ void k_scan(){
  __shared__ int ps[1024];
  int tid = threadIdx.x;
  int base = tid*20;
  int sum = 0;
  for (int j = 0; j < 20; j++){ int i = base + j; if (i < NN) sum += g_cnt[i]; }
  ps[tid] = sum;
  __syncthreads();
  for (int off = 1; off < 1024; off <<= 1){
    int v = (tid >= off) ? ps[tid-off] : 0;
    __syncthreads();
    ps[tid] += v;
    __syncthreads();
  }
  int run = ps[tid] - sum;     // exclusive prefix
  for (int j = 0; j < 20; j++){ int i = base + j; if (i < NN){ g_rowptr[i] = run; run += g_cnt[i]; } }
  if (tid == 0) g_rowptr[NN] = ET;
}
__global__ void k_scatter(const int* __restrict__ ei){
  int e = blockIdx.x*256 + threadIdx.x;
  if (e >= ET) return;
  int d = (e < NE) ? ei[NE + e] : (e - NE);
  int p = atomicAdd(&g_fill[d], 1);
  g_srcs[g_rowptr[d] + p] = e;               // store edge id (sorted below)
}
__global__ void k_sortseg(const int* __restrict__ ei){
  __shared__ int buf[8][128];
  int wid = threadIdx.x >> 5, lane = threadIdx.x & 31;
  int n = blockIdx.x*8 + wid;
  if (n >= NN) return;
  int r0 = g_rowptr[n], r1 = g_rowptr[n+1], d = r1 - r0;
  if (d <= 128){
    for (int j = lane; j < d; j += 32) buf[wid][j] = g_srcs[r0 + j];
    __syncwarp();
    if (lane == 0){
      for (int a = 1; a < d; a++){
        int v = buf[wid][a]; int b = a - 1;
        while (b >= 0 && buf[wid][b] > v){ buf[wid][b+1] = buf[wid][b]; b--; }
        buf[wid][b+1] = v;
      }
    }
    __syncwarp();
    for (int j = lane; j < d; j += 32){
      int id = buf[wid][j];
      g_srcs[r0 + j] = (id < NE) ? ei[id] : (id - NE);
    }
  } else {
    for (int j = lane; j < d; j += 32){
      int id = g_srcs[r0 + j];
      g_srcs[r0 + j] = (id < NE) ? ei[id] : (id - NE);
    }
  }
}

// ---------------- scalar SGEMM: C = A[MxK] @ B[KxN] (+ bias over N) ----------------
__global__ void k_gemm(const float* __restrict__ A, const float* __restrict__ B,
                       const float* __restrict__ bias, float* __restrict__ C,
                       int M, int N, int K){
  __shared__ float As[16][64];
  __shared__ float Bs[16][64];
  int bn = blockIdx.x*64, bm = blockIdx.y*64;
  int tid = threadIdx.x;
  int tx = tid & 15, ty = tid >> 4;
  float acc[4][4];
  #pragma unroll
  for (int i = 0; i < 4; i++)
    #pragma unroll
    for (int j = 0; j < 4; j++) acc[i][j] = 0.f;

  int ar = tid >> 2, ak = (tid & 3) << 2;     // A tile: 64 rows x 16 k
  int bk = tid >> 4, bn2 = (tid & 15) << 2;   // B tile: 16 k x 64 n

  for (int k0 = 0; k0 < K; k0 += 16){
    float4 av = make_float4(0.f,0.f,0.f,0.f);
    if (bm + ar < M) av = *(const float4*)(A + (size_t)(bm + ar)*K + k0 + ak);
    As[ak  ][ar] = av.x; As[ak+1][ar] = av.y; As[ak+2][ar] = av.z; As[ak+3][ar] = av.w;
    float4 bv = make_float4(0.f,0.f,0.f,0.f);
    if (bn + bn2 < N) bv = *(const float4*)(B + (size_t)(k0 + bk)*N + bn + bn2);
    *(float4*)&Bs[bk][bn2] = bv;
    __syncthreads();
    #pragma unroll
    for (int kk = 0; kk < 16; kk++){
      float4 ra = *(const float4*)&As[kk][ty << 2];
      float4 rb = *(const float4*)&Bs[kk][tx << 2];
      float a0 = ra.x, a1 = ra.y, a2 = ra.z, a3 = ra.w;
      acc[0][0] += a0*rb.x; acc[0][1] += a0*rb.y; acc[0][2] += a0*rb.z; acc[0][3] += a0*rb.w;
      acc[1][0] += a1*rb.x; acc[1][1] += a1*rb.y; acc[1][2] += a1*rb.z; acc[1][3] += a1*rb.w;
      acc[2][0] += a2*rb.x; acc[2][1] += a2*rb.y; acc[2][2] += a2*rb.z; acc[2][3] += a2*rb.w;
      acc[3][0] += a3*rb.x; acc[3][1] += a3*rb.y; acc[3][2] += a3*rb.z; acc[3][3] += a3*rb.w;
    }
    __syncthreads();
  }
  #pragma unroll
  for (int i = 0; i < 4; i++){
    int row = bm + (ty << 2) + i;
    if (row >= M) continue;
    #pragma unroll
    for (int j = 0; j < 4; j++){
      int col = bn + (tx << 2) + j;
      if (col >= N) continue;
      float v = acc[i][j];
      if (bias) v += bias[col];
      C[(size_t)row*N + col] = v;
    }
  }
}

// ---------------- attention dots ----------------
__global__ void k_attdot1(const float* __restrict__ aw_s, const float* __restrict__ aw_d){
  int i = blockIdx.x*256 + threadIdx.x;
  if (i >= NN*4) return;
  int n = i >> 2, h = i & 3;
  const float4* hp = (const float4*)(g_h1 + n*256 + h*64);
  const float4* sw = (const float4*)(aw_s + h*64);
  const float4* dw = (const float4*)(aw_d + h*64);
  float s = 0.f, d = 0.f;
  #pragma unroll
  for (int j = 0; j < 16; j++){
    float4 x = hp[j], a = sw[j], b = dw[j];
    s += x.x*a.x + x.y*a.y + x.z*a.z + x.w*a.w;
    d += x.x*b.x + x.y*b.y + x.z*b.z + x.w*b.w;
  }
  g_as1[i] = s; g_ad1[i] = d;
}
__global__ void k_attdot2(const float* __restrict__ aw_s, const float* __restrict__ aw_d){
  int n = blockIdx.x*256 + threadIdx.x;
  if (n >= NN) return;
  const float4* hp = (const float4*)(g_h2 + n*128);
  const float4* sw = (const float4*)aw_s;
  const float4* dw = (const float4*)aw_d;
  float s = 0.f, d = 0.f;
  #pragma unroll
  for (int j = 0; j < 32; j++){
    float4 x = hp[j], a = sw[j], b = dw[j];
    s += x.x*a.x + x.y*a.y + x.z*a.z + x.w*a.w;
    d += x.x*b.x + x.y*b.y + x.z*b.z + x.w*b.w;
  }
  g_as2[n] = s; g_ad2[n] = d;
}

// ---------------- edge softmax + aggregation, layer 1 (4 heads x 64) ----------------
__global__ void k_agg1(const float* __restrict__ bias){
  int wid = threadIdx.x >> 5, lane = threadIdx.x & 31;
  int n = blockIdx.x*8 + wid;
  int r0 = g_rowptr[n], r1 = g_rowptr[n+1];
  float4 ad = *(const float4*)(g_ad1 + n*4);
  float m0 = -1e30f, m1 = -1e30f, m2 = -1e30f, m3 = -1e30f;
  for (int e = r0 + lane; e < r1; e += 32){
    int s = g_srcs[e];
    float4 as = *(const float4*)(g_as1 + s*4);
    float v0 = as.x + ad.x; v0 = v0 > 0.f ? v0 : 0.2f*v0;
    float v1 = as.y + ad.y; v1 = v1 > 0.f ? v1 : 0.2f*v1;
    float v2 = as.z + ad.z; v2 = v2 > 0.f ? v2 : 0.2f*v2;
    float v3 = as.w + ad.w; v3 = v3 > 0.f ? v3 : 0.2f*v3;
    m0 = fmaxf(m0, v0); m1 = fmaxf(m1, v1); m2 = fmaxf(m2, v2); m3 = fmaxf(m3, v3);
  }
  #pragma unroll
  for (int o = 16; o; o >>= 1){
    m0 = fmaxf(m0, __shfl_xor_sync(0xffffffffu, m0, o));
    m1 = fmaxf(m1, __shfl_xor_sync(0xffffffffu, m1, o));
    m2 = fmaxf(m2, __shfl_xor_sync(0xffffffffu, m2, o));
    m3 = fmaxf(m3, __shfl_xor_sync(0xffffffffu, m3, o));
  }
  float s0 = 0.f, s1 = 0.f, s2 = 0.f, s3 = 0.f;
  for (int e = r0 + lane; e < r1; e += 32){
    int s = g_srcs[e];
    float4 as = *(const float4*)(g_as1 + s*4);
    float v0 = as.x + ad.x; v0 = v0 > 0.f ? v0 : 0.2f*v0;
    float v1 = as.y + ad.y; v1 = v1 > 0.f ? v1 : 0.2f*v1;
    float v2 = as.z + ad.z; v2 = v2 > 0.f ? v2 : 0.2f*v2;
    float v3 = as.w + ad.w; v3 = v3 > 0.f ? v3 : 0.2f*v3;
    s0 += __expf(v0 - m0); s1 += __expf(v1 - m1);
    s2 += __expf(v2 - m2); s3 += __expf(v3 - m3);
  }
  #pragma unroll
  for (int o = 16; o; o >>= 1){
    s0 += __shfl_xor_sync(0xffffffffu, s0, o);
    s1 += __shfl_xor_sync(0xffffffffu, s1, o);
    s2 += __shfl_xor_sync(0xffffffffu, s2, o);
    s3 += __shfl_xor_sync(0xffffffffu, s3, o);
  }
  int hsel = lane >> 3;                                    // head owning this lane's 8 channels
  float mh  = hsel == 0 ? m0 : hsel == 1 ? m1 : hsel == 2 ? m2 : m3;
  float inv = 1.f / (hsel == 0 ? s0 : hsel == 1 ? s1 : hsel == 2 ? s2 : s3);
  float adh = hsel == 0 ? ad.x : hsel == 1 ? ad.y : hsel == 2 ? ad.z : ad.w;
  float a0=0,a1=0,a2=0,a3=0,a4=0,a5=0,a6=0,a7=0;
  for (int e = r0; e < r1; e++){
    int s = g_srcs[e];
    float v = g_as1[s*4 + hsel] + adh; v = v > 0.f ? v : 0.2f*v;
    float alpha = __expf(v - mh) * inv;
    const float4* xp = (const float4*)(g_h1 + s*256 + lane*8);
    float4 x0 = xp[0], x1 = xp[1];
    a0 += alpha*x0.x; a1 += alpha*x0.y; a2 += alpha*x0.z; a3 += alpha*x0.w;
    a4 += alpha*x1.x; a5 += alpha*x1.y; a6 += alpha*x1.z; a7 += alpha*x1.w;
  }
  int cb = lane*8;
  float* outp = g_z1 + n*256 + cb;
  float r[8] = {a0,a1,a2,a3,a4,a5,a6,a7};
  #pragma unroll
  for (int i = 0; i < 8; i++){
    float o = r[i] + bias[cb + i];
    outp[i] = o > 0.f ? o : expm1f(o);                     // ELU
  }
}

// ---------------- edge softmax + aggregation, layer 2 (1 head x 128) ----------------
__global__ void k_agg2(const float* __restrict__ bias){
  int wid = threadIdx.x >> 5, lane = threadIdx.x & 31;
  int n = blockIdx.x*8 + wid;
  int r0 = g_rowptr[n], r1 = g_rowptr[n+1];
  float ad = g_ad2[n];
  float m = -1e30f;
  for (int e = r0 + lane; e < r1; e += 32){
    float v = g_as2[g_srcs[e]] + ad; v = v > 0.f ? v : 0.2f*v;
    m = fmaxf(m, v);
  }
  #pragma unroll
  for (int o = 16; o; o >>= 1) m = fmaxf(m, __shfl_xor_sync(0xffffffffu, m, o));
  float ssum = 0.f;
  for (int e = r0 + lane; e < r1; e += 32){
    float v = g_as2[g_srcs[e]] + ad; v = v > 0.f ? v : 0.2f*v;
    ssum += __expf(v - m);
  }
  #pragma unroll
  for (int o = 16; o; o >>= 1) ssum += __shfl_xor_sync(0xffffffffu, ssum, o);
  float inv = 1.f / ssum;
  float a0=0,a1=0,a2=0,a3=0;
  for (int e = r0; e < r1; e++){
    int s = g_srcs[e];
    float v = g_as2[s] + ad; v = v > 0.f ? v : 0.2f*v;
    float alpha = __expf(v - m) * inv;
    float4 x = *(const float4*)(g_h2 + s*128 + lane*4);
    a0 += alpha*x.x; a1 += alpha*x.y; a2 += alpha*x.z; a3 += alpha*x.w;
  }
  int cb = lane*4;
  float* outp = g_z2 + n*128 + cb;
  outp[0] = a0 + bias[cb+0];
  outp[1] = a1 + bias[cb+1];
  outp[2] = a2 + bias[cb+2];
  outp[3] = a3 + bias[cb+3];
}

// ---------------- sequence gather (forward + reversed-within-length) ----------------
__global__ void k_gather(const int* __restrict__ seq, const int* __restrict__ lengths){
  int i = blockIdx.x*256 + threadIdx.x;                    // one float4 per thread
  if (i >= BB*TT*32) return;
  int row = i >> 5, q = i & 31;
  int b = row / TT, t = row - b*TT;
  const float4* z = (const float4*)g_z2;
  int sf = seq[row];
  ((float4*)g_seqg[0])[row*32 + q] = z[(size_t)sf*32 + q];
  int len = lengths[b];
  int tr = len - 1 - t; if (tr < 0) tr = 0;
  int sb = seq[b*TT + tr];
  ((float4*)g_seqg[1])[row*32 + q] = z[(size_t)sb*32 + q];
}

// ---------------- BiLSTM recurrence ----------------
__global__ void __launch_bounds__(512, 1)
k_lstm(const float* __restrict__ whhf, const float* __restrict__ whhb,
       const int* __restrict__ lengths){
  extern __shared__ char smraw[];
  ull*   ws  = (ull*)smraw;                 // [512][33] packed f32x2 weight pairs (k 64..127)
  float* hsm = (float*)(ws + 512*33);       // [2][128]
  float* gsm = hsm + 256;                   // [2][512]
  int g   = threadIdx.x;
  int dir = blockIdx.y;
  int b0  = blockIdx.x*2;
  const float* whh = dir ? whhb : whhf;
  const ull* wrow = (const ull*)(whh + g*128);
  ull wreg[32];
  #pragma unroll
  for (int j = 0; j < 32; j++) wreg[j] = wrow[j];          // k pairs 0..31
  #pragma unroll
  for (int j = 0; j < 32; j++) ws[g*33 + j] = wrow[32 + j];// k pairs 32..63
  if (g < 256) hsm[g] = 0.f;
  float cc = 0.f;
  int len0 = lengths[b0], len1 = lengths[b0+1];
  int Tn = len0 > len1 ? len0 : len1;       // both dirs: t >= len has zero softmax weight
  const float* x0p = g_xproj[dir] + (size_t)b0*TT*512;
  const float* x1p = x0p + (size_t)TT*512;
  __syncthreads();
  for (int t = 0; t < Tn; t++){
    float xv0 = x0p[t*512 + g];
    float xv1 = x1p[t*512 + g];
    ull a0 = 0ULL, a1 = 0ULL;
    const ull* h0p = (const ull*)hsm;
    const ull* h1p = (const ull*)(hsm + 128);
    #pragma unroll
    for (int j = 0; j < 32; j++){
      ull w = wreg[j];
      a0 = fma2(w, h0p[j], a0);
      a1 = fma2(w, h1p[j], a1);
    }
    #pragma unroll
    for (int j = 0; j < 32; j++){
      ull w = ws[g*33 + j];
      a0 = fma2(w, h0p[32 + j], a0);
      a1 = fma2(w, h1p[32 + j], a1);
    }
    gsm[g]       = hsum2(a0) + xv0;
    gsm[512 + g] = hsum2(a1) + xv1;
    __syncthreads();
    if (g < 256){
      int b = g >> 7, j = g & 127;
      const float* gb = gsm + b*512;
      float gi = gb[j], gf = gb[128 + j], gg = gb[256 + j], go = gb[384 + j];
      cc = sigf(gf)*cc + sigf(gi)*tanhf(gg);
      float h = sigf(go)*tanhf(cc);
      hsm[b*128 + j] = h;
      if (dir == 0){
        if (t < (b ? len1 : len0))
          g_lstm[((size_t)(b0 + b)*TT + t)*256 + j] = h;
      } else {
        int L = b ? len1 : len0;
        if (t < L) g_lstm[((size_t)(b0 + b)*TT + (L - 1 - t))*256 + 128 + j] = h;
      }
    }
    __syncthreads();
  }
}

// ---------------- masked attention pooling (both heads) ----------------
__global__ void k_attnpool(const float* __restrict__ wn, const float* __restrict__ bn,
                           const float* __restrict__ wsp, const float* __restrict__ bsp,
                           const int* __restrict__ lengths){
  __shared__ float sc[256];
  __shared__ float red[256];
  int b = blockIdx.x, p = blockIdx.y;
  const float* w = p ? wsp : wn;
  float bias = p ? bsp[0] : bn[0];
  int tid = threadIdx.x;
  int len = lengths[b];
  float sv = -1e30f;
  if (tid < TT && tid < len){
    const float4* row = (const float4*)(g_lstm + ((size_t)b*TT + tid)*256);
    const float4* wv = (const float4*)w;
    float s = 0.f;
    #pragma unroll
    for (int j = 0; j < 64; j++){
      float4 x = row[j], y = wv[j];
      s += x.x*y.x + x.y*y.y + x.z*y.z + x.w*y.w;
    }
    sv = s + bias;
  }
  red[tid] = sv;
  __syncthreads();
  #pragma unroll
  for (int o = 128; o; o >>= 1){ if (tid < o) red[tid] = fmaxf(red[tid], red[tid+o]); __syncthreads(); }
  float m = red[0];
  __syncthreads();
  float e = (sv <= -1e29f) ? 0.f : __expf(sv - m);
  sc[tid] = e; red[tid] = e;
  __syncthreads();
  #pragma unroll
  for (int o = 128; o; o >>= 1){ if (tid < o) red[tid] += red[tid+o]; __syncthreads(); }
  float inv = 1.f / red[0];
  float acc = 0.f;
  for (int t = 0; t < TT; t++)
    acc += sc[t] * g_lstm[((size_t)b*TT + t)*256 + tid];
  g_ctx[p][b*256 + tid] = acc * inv;
}

// ---------------- launch ----------------
extern "C" void kernel_launch(void* const* d_in, const int* in_sizes, int n_in,
                              void* d_out, int out_size){
  const float* xc   = (const float*)d_in[0];
  const float* tf   = (const float*)d_in[1];
  const float* emb  = (const float*)d_in[2];
  const float* g1W  = (const float*)d_in[3];
  const float* g1as = (const float*)d_in[4];
  const float* g1ad = (const float*)d_in[5];
  const float* g1b  = (const float*)d_in[6];
  const float* g2W  = (const float*)d_in[7];
  const float* g2as = (const float*)d_in[8];
  const float* g2ad = (const float*)d_in[9];
  const float* g2b  = (const float*)d_in[10];
  const float* wihf = (const float*)d_in[11];
  const float* whhf = (const float*)d_in[12];
  const float* bf   = (const float*)d_in[13];
  const float* wihb = (const float*)d_in[14];
  const float* whhb = (const float*)d_in[15];
  const float* bb   = (const float*)d_in[16];
  const float* anw  = (const float*)d_in[17];
  const float* anb  = (const float*)d_in[18];
  const float* asw  = (const float*)d_in[19];
  const float* asb  = (const float*)d_in[20];
  const float* fnW  = (const float*)d_in[21];
  const float* fnb  = (const float*)d_in[22];
  const float* fsW  = (const float*)d_in[23];
  const float* fsb  = (const float*)d_in[24];
  const int*   ei   = (const int*)d_in[25];
  const int*   seq  = (const int*)d_in[26];
  const int*   len  = (const int*)d_in[27];
  float* out = (float*)d_out;

  float *p_nf, *p_w1p, *p_h1, *p_z1, *p_h2, *p_wT, *p_sq, *p_xp, *p_ctx, *p_lstm;
  cudaGetSymbolAddress((void**)&p_nf,  g_nf);
  cudaGetSymbolAddress((void**)&p_w1p, g_w1p);
  cudaGetSymbolAddress((void**)&p_h1,  g_h1);
  cudaGetSymbolAddress((void**)&p_z1,  g_z1);
  cudaGetSymbolAddress((void**)&p_h2,  g_h2);
  cudaGetSymbolAddress((void**)&p_wT,  g_wTih);
  cudaGetSymbolAddress((void**)&p_sq,  g_seqg);
  cudaGetSymbolAddress((void**)&p_xp,  g_xproj);
  cudaGetSymbolAddress((void**)&p_ctx, g_ctx);
  cudaGetSymbolAddress((void**)&p_lstm, g_lstm);

  // launch order puts the big GAT1 GEMM at our kernel-launch index 3 so the
  // fixed ncu window (-s 5, two harness-internal launches precede ours)
  // profiles it instead of a trivial CSR kernel.
  k_prep<<<11250, 256>>>(xc, tf, emb, g1W, wihf, wihb);                       // 0
  k_zero_cnt<<<(NN+255)/256, 256>>>();                                        // 1
  k_count<<<(ET+255)/256, 256>>>(ei);                                         // 2
  k_gemm<<<dim3(4, 313), 256>>>(p_nf, p_w1p, nullptr, p_h1, NN, 256, 144);    // 3  <- profiled
  k_scan<<<1, 1024>>>();                                                      // 4
  k_scatter<<<(ET+255)/256, 256>>>(ei);                                       // 5
  k_sortseg<<<2500, 256>>>(ei);                                               // 6
  cudaMemsetAsync(p_lstm, 0, (size_t)BB*TT*256*sizeof(float));                // memset node

  // GAT layer 1 (GEMM already issued above)
  k_attdot1<<<(NN*4+255)/256, 256>>>(g1as, g1ad);
  k_agg1<<<2500, 256>>>(g1b);

  // GAT layer 2
  k_gemm<<<dim3(2, 313), 256>>>(p_z1, g2W, nullptr, p_h2, NN, 128, 256);
  k_attdot2<<<(NN+255)/256, 256>>>(g2as, g2ad);
  k_agg2<<<2500, 256>>>(g2b);

  // gather + x-projections (bias folded in)
  k_gather<<<3200, 256>>>(seq, len);
  k_gemm<<<dim3(8, 400), 256>>>(p_sq,               p_wT,           bf, p_xp,               BB*TT, 512, 128);
  k_gemm<<<dim3(8, 400), 256>>>(p_sq + BB*TT*128,   p_wT + 128*512, bb, p_xp + BB*TT*512,   BB*TT, 512, 128);

  // BiLSTM
  int lstm_smem = 512*33*8 + 256*4 + 1024*4;
  cudaFuncSetAttribute(k_lstm, cudaFuncAttributeMaxDynamicSharedMemorySize, lstm_smem);
  k_lstm<<<dim3(64, 2), 512, lstm_smem>>>(whhf, whhb, len);

  // attention pooling + output heads
  k_attnpool<<<dim3(BB, 2), 256>>>(anw, anb, asw, asb, len);
  k_gemm<<<dim3(313, 2), 256>>>(p_ctx,          fnW, fnb, out,                    BB, 20000, 256);
  k_gemm<<<dim3(1, 2),   256>>>(p_ctx + BB*256, fsW, fsb, out + (size_t)BB*20000, BB, 64,    256);
}